// round 6
// baseline (speedup 1.0000x reference)
#include <cuda_runtime.h>
#include <cstdint>

#define T_TOK 4096
#define HID   1024
#define NEXP  8
#define FFN   4096
#define TOPK  2
#define NSLOT (T_TOK*TOPK)   /* 8192, fixed regardless of routing */

// ---------------- static scratch (no allocations allowed) ----------------
__device__ float d_h1[(size_t)NSLOT * FFN];   // 128 MB; reused as g after GLU
__device__ float d_h2[(size_t)NSLOT * FFN];   // 128 MB
__device__ float d_y [(size_t)NSLOT * HID];   // 32 MB
__device__ int   d_cnt[NEXP];
__device__ int   d_off[NEXP];
__device__ int   d_cur[NEXP];
__device__ int   d_rowidx[NSLOT];
__device__ int   d_tokeid[T_TOK * TOPK];
__device__ int   d_tokslot[T_TOK * TOPK];
__device__ float d_tokw[T_TOK * TOPK];

// ---------------- helpers ----------------
__device__ __forceinline__ unsigned f2tf(float v) {
    unsigned r;
    asm("cvt.rna.tf32.f32 %0, %1;" : "=r"(r) : "f"(v));
    return r;
}

__device__ __forceinline__ void tf_split(float v, unsigned& hi, unsigned& lo) {
    hi = f2tf(v);
    lo = f2tf(v - __uint_as_float(hi));
}

__device__ __forceinline__ void mma8(float* c, const unsigned* a, unsigned b0, unsigned b1) {
    asm volatile(
        "mma.sync.aligned.m16n8k8.row.col.f32.tf32.tf32.f32 "
        "{%0,%1,%2,%3},{%4,%5,%6,%7},{%8,%9},{%0,%1,%2,%3};"
        : "+f"(c[0]), "+f"(c[1]), "+f"(c[2]), "+f"(c[3])
        : "r"(a[0]), "r"(a[1]), "r"(a[2]), "r"(a[3]), "r"(b0), "r"(b1));
}

__device__ __forceinline__ float gelu_tanh(float x) {
    float x3 = x * x * x;
    float t = tanhf(0.7978845608028654f * (x + 0.044715f * x3));
    return 0.5f * x * (1.0f + t);
}

// ---------------- kernel 0: zero counts ----------------
__global__ void k_init() {
    if (threadIdx.x < NEXP) d_cnt[threadIdx.x] = 0;
}

// ---------------- kernel 1: router (one warp per token) ----------------
__global__ void k_router(const float* __restrict__ x, const float* __restrict__ rw) {
    int gw   = (blockIdx.x * blockDim.x + threadIdx.x) >> 5;
    int lane = threadIdx.x & 31;
    if (gw >= T_TOK) return;

    const float4* xr = reinterpret_cast<const float4*>(x + (size_t)gw * HID);
    float4 xf[8];
#pragma unroll
    for (int i = 0; i < 8; i++) xf[i] = xr[lane + 32 * i];

    float p[NEXP];
#pragma unroll
    for (int e = 0; e < NEXP; e++) {
        const float4* wr = reinterpret_cast<const float4*>(rw + (size_t)e * HID);
        float s = 0.f;
#pragma unroll
        for (int i = 0; i < 8; i++) {
            float4 w = wr[lane + 32 * i];
            s = fmaf(xf[i].x, w.x, s);
            s = fmaf(xf[i].y, w.y, s);
            s = fmaf(xf[i].z, w.z, s);
            s = fmaf(xf[i].w, w.w, s);
        }
#pragma unroll
        for (int o = 16; o > 0; o >>= 1) s += __shfl_xor_sync(0xffffffffu, s, o);
        p[e] = s;   // logits
    }

    if (lane == 0) {
        // top-2 on logits, strict > keeps lowest index (matches lax.top_k ties)
        int i0 = 0;
#pragma unroll
        for (int e = 1; e < NEXP; e++) if (p[e] > p[i0]) i0 = e;
        int i1 = (i0 == 0) ? 1 : 0;
#pragma unroll
        for (int e = 0; e < NEXP; e++) if (e != i0 && p[e] > p[i1]) i1 = e;

        float mx = p[i0];
        float den = 0.f, pe[NEXP];
#pragma unroll
        for (int e = 0; e < NEXP; e++) { pe[e] = expf(p[e] - mx); den += pe[e]; }
        float w0 = pe[i0] / den, w1 = pe[i1] / den;

        d_tokeid[2 * gw]     = i0;
        d_tokeid[2 * gw + 1] = i1;
        d_tokw[2 * gw]       = w0;
        d_tokw[2 * gw + 1]   = w1;
        atomicAdd(&d_cnt[i0], 1);
        atomicAdd(&d_cnt[i1], 1);
    }
}

// ---------------- kernel 2: exclusive prefix offsets ----------------
__global__ void k_offsets() {
    if (threadIdx.x == 0) {
        int s = 0;
        for (int e = 0; e < NEXP; e++) { d_off[e] = s; s += d_cnt[e]; }
    }
    if (threadIdx.x < NEXP) d_cur[threadIdx.x] = 0;
}

// ---------------- kernel 3: slot assignment ----------------
__global__ void k_assign() {
    int t = blockIdx.x * blockDim.x + threadIdx.x;
    if (t >= T_TOK) return;
#pragma unroll
    for (int k = 0; k < TOPK; k++) {
        int e   = d_tokeid[2 * t + k];
        int pos = atomicAdd(&d_cur[e], 1);
        int slot = d_off[e] + pos;
        d_rowidx[slot]       = t;
        d_tokslot[2 * t + k] = slot;
    }
}

// ---------------- GEMM1: h = Xg @ W^T  (gathered A, B=[F][H]) ----------------
// 3xTF32, BM=128 BN=64 BK=16, 128 threads (4 warps, 2x2), warp tile 64x32.
__global__ __launch_bounds__(128) void k_gemm1(const float* __restrict__ X,
                                               const float* __restrict__ Bw,
                                               int which) {
    const int e     = blockIdx.z;
    const int cnt   = d_cnt[e];
    const int mbase = blockIdx.y * 128;
    if (mbase >= cnt) return;
    const int n0       = blockIdx.x * 64;
    const int slotbase = d_off[e] + mbase;
    float* __restrict__ outp = which ? d_h2 : d_h1;

    __shared__ float As[2][128][20];
    __shared__ float Bs[2][64][20];
    __shared__ int   rs[128];

    const int tid  = threadIdx.x;
    const int lane = tid & 31;
    const int warp = tid >> 5;
    const int g    = lane >> 2;
    const int tg   = lane & 3;
    const int wm   = warp >> 1;
    const int wn   = warp & 1;

    {
        int s = slotbase + tid;
        rs[tid] = d_rowidx[min(s, NSLOT - 1)];
    }
    __syncthreads();

    const float* Be = Bw + (size_t)e * FFN * HID;

    float acc[4][4][4];
#pragma unroll
    for (int i = 0; i < 4; i++)
#pragma unroll
        for (int j = 0; j < 4; j++)
#pragma unroll
            for (int c = 0; c < 4; c++) acc[i][j][c] = 0.f;

    float4 va[4], vb[2];
    const int KT = HID / 16;  // 64

    // prologue load
    {
        int k0 = 0;
#pragma unroll
        for (int p = 0; p < 4; p++) {
            int row = (tid >> 2) + 32 * p;
            va[p] = *((const float4*)(X + (size_t)rs[row] * HID + k0) + (tid & 3));
        }
#pragma unroll
        for (int p = 0; p < 2; p++) {
            int idx = tid + 128 * p, row = idx >> 2, c4 = idx & 3;
            vb[p] = *((const float4*)(Be + (size_t)(n0 + row) * HID + k0) + c4);
        }
#pragma unroll
        for (int p = 0; p < 4; p++) {
            int row = (tid >> 2) + 32 * p;
            *(float4*)&As[0][row][(tid & 3) * 4] = va[p];
        }
#pragma unroll
        for (int p = 0; p < 2; p++) {
            int idx = tid + 128 * p, row = idx >> 2, c4 = idx & 3;
            *(float4*)&Bs[0][row][c4 * 4] = vb[p];
        }
    }
    __syncthreads();

    for (int kt = 0; kt < KT; kt++) {
        const int buf = kt & 1;
        if (kt + 1 < KT) {
            int k0 = (kt + 1) * 16;
#pragma unroll
            for (int p = 0; p < 4; p++) {
                int row = (tid >> 2) + 32 * p;
                va[p] = *((const float4*)(X + (size_t)rs[row] * HID + k0) + (tid & 3));
            }
#pragma unroll
            for (int p = 0; p < 2; p++) {
                int idx = tid + 128 * p, row = idx >> 2, c4 = idx & 3;
                vb[p] = *((const float4*)(Be + (size_t)(n0 + row) * HID + k0) + c4);
            }
        }

#pragma unroll
        for (int ks = 0; ks < 2; ks++) {
            const int kk = ks * 8 + tg;
            unsigned ah[4][4], al[4][4];
            unsigned bh[4][2], bl[4][2];
#pragma unroll
            for (int mt = 0; mt < 4; mt++) {
                int r = wm * 64 + mt * 16 + g;
                float a0 = As[buf][r][kk];
                float a1 = As[buf][r + 8][kk];
                float a2 = As[buf][r][kk + 4];
                float a3 = As[buf][r + 8][kk + 4];
                tf_split(a0, ah[mt][0], al[mt][0]);
                tf_split(a1, ah[mt][1], al[mt][1]);
                tf_split(a2, ah[mt][2], al[mt][2]);
                tf_split(a3, ah[mt][3], al[mt][3]);
            }
#pragma unroll
            for (int nt = 0; nt < 4; nt++) {
                int c = wn * 32 + nt * 8 + g;
                float b0 = Bs[buf][c][kk];
                float b1 = Bs[buf][c][kk + 4];
                tf_split(b0, bh[nt][0], bl[nt][0]);
                tf_split(b1, bh[nt][1], bl[nt][1]);
            }
#pragma unroll
            for (int mt = 0; mt < 4; mt++)
#pragma unroll
                for (int nt = 0; nt < 4; nt++) {
                    mma8(acc[mt][nt], ah[mt], bl[nt][0], bl[nt][1]);
                    mma8(acc[mt][nt], al[mt], bh[nt][0], bh[nt][1]);
                    mma8(acc[mt][nt], ah[mt], bh[nt][0], bh[nt][1]);
                }
        }

        if (kt + 1 < KT) {
            int nbuf = buf ^ 1;
#pragma unroll
            for (int p = 0; p < 4; p++) {
                int row = (tid >> 2) + 32 * p;
                *(float4*)&As[nbuf][row][(tid & 3) * 4] = va[p];
            }
#pragma unroll
            for (int p = 0; p < 2; p++) {
                int idx = tid + 128 * p, row = idx >> 2, c4 = idx & 3;
                *(float4*)&Bs[nbuf][row][c4 * 4] = vb[p];
            }
        }
        __syncthreads();
    }

    const int mrem = cnt - mbase;
#pragma unroll
    for (int mt = 0; mt < 4; mt++) {
#pragma unroll
        for (int half = 0; half < 2; half++) {
            int m = wm * 64 + mt * 16 + g + half * 8;
            if (m < mrem) {
                float* orow = outp + (size_t)(slotbase + m) * FFN + n0;
#pragma unroll
                for (int nt = 0; nt < 4; nt++) {
                    int c = wn * 32 + nt * 8 + 2 * tg;
                    float2 v = make_float2(acc[mt][nt][half * 2], acc[mt][nt][half * 2 + 1]);
                    *(float2*)(orow + c) = v;
                }
            }
        }
    }
}

// ---------------- GLU: g = gelu(h1) * h2 (in-place into d_h1) ----------------
__global__ void k_glu() {
    size_t i = (size_t)blockIdx.x * blockDim.x + threadIdx.x;
    const size_t n4 = (size_t)NSLOT * FFN / 4;
    if (i >= n4) return;
    float4 a = ((const float4*)d_h1)[i];
    float4 b = ((const float4*)d_h2)[i];
    a.x = gelu_tanh(a.x) * b.x;
    a.y = gelu_tanh(a.y) * b.y;
    a.z = gelu_tanh(a.z) * b.z;
    a.w = gelu_tanh(a.w) * b.w;
    ((float4*)d_h1)[i] = a;
}

// ---------------- GEMM2: y = g @ W2  (A direct, B=[F][H] k-major) ----------------
__global__ __launch_bounds__(128) void k_gemm2(const float* __restrict__ W2) {
    const int e     = blockIdx.z;
    const int cnt   = d_cnt[e];
    const int mbase = blockIdx.y * 128;
    if (mbase >= cnt) return;
    const int n0       = blockIdx.x * 64;
    const int slotbase = d_off[e] + mbase;

    __shared__ float As[2][128][20];
    __shared__ float Bs[2][16][72];

    const int tid  = threadIdx.x;
    const int lane = tid & 31;
    const int warp = tid >> 5;
    const int g    = lane >> 2;
    const int tg   = lane & 3;
    const int wm   = warp >> 1;
    const int wn   = warp & 1;

    const float* Be = W2 + (size_t)e * FFN * HID;
    const float* Gp = d_h1;

    // precompute clamped A rows for this thread
    int arows[4];
#pragma unroll
    for (int p = 0; p < 4; p++) {
        int grow = slotbase + (tid >> 2) + 32 * p;
        arows[p] = min(grow, NSLOT - 1);
    }

    float acc[4][4][4];
#pragma unroll
    for (int i = 0; i < 4; i++)
#pragma unroll
        for (int j = 0; j < 4; j++)
#pragma unroll
            for (int c = 0; c < 4; c++) acc[i][j][c] = 0.f;

    float4 va[4], vb[2];
    const int KT = FFN / 16;  // 256

    {
        int k0 = 0;
#pragma unroll
        for (int p = 0; p < 4; p++)
            va[p] = *((const float4*)(Gp + (size_t)arows[p] * FFN + k0) + (tid & 3));
#pragma unroll
        for (int p = 0; p < 2; p++) {
            int idx = tid + 128 * p, row = idx >> 4, c4 = idx & 15;
            vb[p] = *((const float4*)(Be + (size_t)(k0 + row) * HID + n0) + c4);
        }
#pragma unroll
        for (int p = 0; p < 4; p++) {
            int row = (tid >> 2) + 32 * p;
            *(float4*)&As[0][row][(tid & 3) * 4] = va[p];
        }
#pragma unroll
        for (int p = 0; p < 2; p++) {
            int idx = tid + 128 * p, row = idx >> 4, c4 = idx & 15;
            *(float4*)&Bs[0][row][c4 * 4] = vb[p];
        }
    }
    __syncthreads();

    for (int kt = 0; kt < KT; kt++) {
        const int buf = kt & 1;
        if (kt + 1 < KT) {
            int k0 = (kt + 1) * 16;
#pragma unroll
            for (int p = 0; p < 4; p++)
                va[p] = *((const float4*)(Gp + (size_t)arows[p] * FFN + k0) + (tid & 3));
#pragma unroll
            for (int p = 0; p < 2; p++) {
                int idx = tid + 128 * p, row = idx >> 4, c4 = idx & 15;
                vb[p] = *((const float4*)(Be + (size_t)(k0 + row) * HID + n0) + c4);
            }
        }

#pragma unroll
        for (int ks = 0; ks < 2; ks++) {
            const int kk = ks * 8 + tg;
            unsigned ah[4][4], al[4][4];
            unsigned bh[4][2], bl[4][2];
#pragma unroll
            for (int mt = 0; mt < 4; mt++) {
                int r = wm * 64 + mt * 16 + g;
                float a0 = As[buf][r][kk];
                float a1 = As[buf][r + 8][kk];
                float a2 = As[buf][r][kk + 4];
                float a3 = As[buf][r + 8][kk + 4];
                tf_split(a0, ah[mt][0], al[mt][0]);
                tf_split(a1, ah[mt][1], al[mt][1]);
                tf_split(a2, ah[mt][2], al[mt][2]);
                tf_split(a3, ah[mt][3], al[mt][3]);
            }
#pragma unroll
            for (int nt = 0; nt < 4; nt++) {
                int c = wn * 32 + nt * 8 + g;
                float b0 = Bs[buf][kk][c];
                float b1 = Bs[buf][kk + 4][c];
                tf_split(b0, bh[nt][0], bl[nt][0]);
                tf_split(b1, bh[nt][1], bl[nt][1]);
            }
#pragma unroll
            for (int mt = 0; mt < 4; mt++)
#pragma unroll
                for (int nt = 0; nt < 4; nt++) {
                    mma8(acc[mt][nt], ah[mt], bl[nt][0], bl[nt][1]);
                    mma8(acc[mt][nt], al[mt], bh[nt][0], bh[nt][1]);
                    mma8(acc[mt][nt], ah[mt], bh[nt][0], bh[nt][1]);
                }
        }

        if (kt + 1 < KT) {
            int nbuf = buf ^ 1;
#pragma unroll
            for (int p = 0; p < 4; p++) {
                int row = (tid >> 2) + 32 * p;
                *(float4*)&As[nbuf][row][(tid & 3) * 4] = va[p];
            }
#pragma unroll
            for (int p = 0; p < 2; p++) {
                int idx = tid + 128 * p, row = idx >> 4, c4 = idx & 15;
                *(float4*)&Bs[nbuf][row][c4 * 4] = vb[p];
            }
        }
        __syncthreads();
    }

    const int mrem = cnt - mbase;
#pragma unroll
    for (int mt = 0; mt < 4; mt++) {
#pragma unroll
        for (int half = 0; half < 2; half++) {
            int m = wm * 64 + mt * 16 + g + half * 8;
            if (m < mrem) {
                float* orow = d_y + (size_t)(slotbase + m) * HID + n0;
#pragma unroll
                for (int nt = 0; nt < 4; nt++) {
                    int c = wn * 32 + nt * 8 + 2 * tg;
                    float2 v = make_float2(acc[mt][nt][half * 2], acc[mt][nt][half * 2 + 1]);
                    *(float2*)(orow + c) = v;
                }
            }
        }
    }
}

// ---------------- combine: out[t] = w0*y[s0] + w1*y[s1] ----------------
__global__ void k_combine(float* __restrict__ out) {
    int idx = blockIdx.x * blockDim.x + threadIdx.x;
    const int n4 = T_TOK * (HID / 4);
    if (idx >= n4) return;
    int t = idx / (HID / 4);
    int h = idx - t * (HID / 4);
    int s0 = d_tokslot[2 * t];
    int s1 = d_tokslot[2 * t + 1];
    float w0 = d_tokw[2 * t];
    float w1 = d_tokw[2 * t + 1];
    float4 y0 = ((const float4*)d_y)[(size_t)s0 * (HID / 4) + h];
    float4 y1 = ((const float4*)d_y)[(size_t)s1 * (HID / 4) + h];
    float4 o;
    o.x = w0 * y0.x + w1 * y1.x;
    o.y = w0 * y0.y + w1 * y1.y;
    o.z = w0 * y0.z + w1 * y1.z;
    o.w = w0 * y0.w + w1 * y1.w;
    ((float4*)out)[idx] = o;
}

// ---------------- launch ----------------
extern "C" void kernel_launch(void* const* d_in, const int* in_sizes, int n_in,
                              void* d_out, int out_size) {
    (void)in_sizes; (void)n_in; (void)out_size;
    const float* x  = (const float*)d_in[0];
    const float* rw = (const float*)d_in[1];
    const float* w1 = (const float*)d_in[2];
    const float* v1 = (const float*)d_in[3];
    const float* w2 = (const float*)d_in[4];
    float* out = (float*)d_out;

    k_init<<<1, 32>>>();
    k_router<<<T_TOK / 4, 128>>>(x, rw);
    k_offsets<<<1, 32>>>();
    k_assign<<<T_TOK / 256, 256>>>();

    dim3 g1(FFN / 64, 32, NEXP);
    k_gemm1<<<g1, 128>>>(x, w1, 0);
    k_gemm1<<<g1, 128>>>(x, v1, 1);

    k_glu<<<(NSLOT * (FFN / 4)) / 256, 256>>>();

    dim3 g2(HID / 64, 32, NEXP);
    k_gemm2<<<g2, 128>>>(w2);

    k_combine<<<(T_TOK * (HID / 4)) / 256, 256>>>(out);
}

// round 10
// speedup vs baseline: 1.2736x; 1.2736x over previous
#include <cuda_runtime.h>
#include <cuda_bf16.h>
#include <cstdint>

#define T_TOK 4096
#define HID   1024
#define NEXP  8
#define FFN   4096
#define TOPK  2
#define NSLOT (T_TOK*TOPK)   /* 8192, fixed: every slot is a real (token,expert) pair */

// ---------------- static scratch (no allocations allowed) ----------------
__device__ float d_h1[(size_t)NSLOT * FFN];
__device__ float d_h2[(size_t)NSLOT * FFN];
__device__ __nv_bfloat16 d_gh[(size_t)NSLOT * FFN];
__device__ __nv_bfloat16 d_gl[(size_t)NSLOT * FFN];
__device__ float d_y[(size_t)NSLOT * HID];
__device__ int   d_cnt[NEXP];
__device__ int   d_off[NEXP];
__device__ int   d_cur[NEXP];
__device__ int   d_rowidx[NSLOT];
__device__ int   d_tokeid[T_TOK * TOPK];
__device__ int   d_tokslot[T_TOK * TOPK];
__device__ float d_tokw[T_TOK * TOPK];

// ---------------- helpers ----------------
__device__ __forceinline__ uint32_t s2u(const void* p) {
    uint32_t r;
    asm("{ .reg .u64 t; cvta.to.shared.u64 t, %1; cvt.u32.u64 %0, t; }" : "=r"(r) : "l"(p));
    return r;
}

#define LDSM_X4(r0, r1, r2, r3, addr) \
    asm volatile("ldmatrix.sync.aligned.m8n8.x4.shared.b16 {%0,%1,%2,%3}, [%4];" \
                 : "=r"(r0), "=r"(r1), "=r"(r2), "=r"(r3) : "r"(addr))

#define LDSM_X4T(r0, r1, r2, r3, addr) \
    asm volatile("ldmatrix.sync.aligned.m8n8.x4.trans.shared.b16 {%0,%1,%2,%3}, [%4];" \
                 : "=r"(r0), "=r"(r1), "=r"(r2), "=r"(r3) : "r"(addr))

#define MMA16816(c, a, b0, b1) \
    asm volatile("mma.sync.aligned.m16n8k16.row.col.f32.bf16.bf16.f32 " \
                 "{%0,%1,%2,%3},{%4,%5,%6,%7},{%8,%9},{%0,%1,%2,%3};" \
                 : "+f"((c)[0]), "+f"((c)[1]), "+f"((c)[2]), "+f"((c)[3]) \
                 : "r"((a)[0]), "r"((a)[1]), "r"((a)[2]), "r"((a)[3]), "r"(b0), "r"(b1))

__device__ __forceinline__ float gelu_tanh(float x) {
    float x3 = x * x * x;
    float t = tanhf(0.7978845608028654f * (x + 0.044715f * x3));
    return 0.5f * x * (1.0f + t);
}

// split float4 -> 4 bf16 hi (uint2) + 4 bf16 lo (uint2)
__device__ __forceinline__ void cvt4(float4 v, uint2& h, uint2& l) {
    __nv_bfloat16 hx = __float2bfloat16(v.x), hy = __float2bfloat16(v.y);
    __nv_bfloat16 hz = __float2bfloat16(v.z), hw = __float2bfloat16(v.w);
    __nv_bfloat16 lx = __float2bfloat16(v.x - __bfloat162float(hx));
    __nv_bfloat16 ly = __float2bfloat16(v.y - __bfloat162float(hy));
    __nv_bfloat16 lz = __float2bfloat16(v.z - __bfloat162float(hz));
    __nv_bfloat16 lw = __float2bfloat16(v.w - __bfloat162float(hw));
    h.x = ((uint32_t)__bfloat16_as_ushort(hy) << 16) | __bfloat16_as_ushort(hx);
    h.y = ((uint32_t)__bfloat16_as_ushort(hw) << 16) | __bfloat16_as_ushort(hz);
    l.x = ((uint32_t)__bfloat16_as_ushort(ly) << 16) | __bfloat16_as_ushort(lx);
    l.y = ((uint32_t)__bfloat16_as_ushort(lw) << 16) | __bfloat16_as_ushort(lz);
}

// ---------------- routing kernels (proven in R2-R6) ----------------
__global__ void k_init() {
    if (threadIdx.x < NEXP) d_cnt[threadIdx.x] = 0;
}

__global__ void k_router(const float* __restrict__ x, const float* __restrict__ rw) {
    int gw   = (blockIdx.x * blockDim.x + threadIdx.x) >> 5;
    int lane = threadIdx.x & 31;
    if (gw >= T_TOK) return;

    const float4* xr = reinterpret_cast<const float4*>(x + (size_t)gw * HID);
    float4 xf[8];
#pragma unroll
    for (int i = 0; i < 8; i++) xf[i] = xr[lane + 32 * i];

    float p[NEXP];
#pragma unroll
    for (int e = 0; e < NEXP; e++) {
        const float4* wr = reinterpret_cast<const float4*>(rw + (size_t)e * HID);
        float s = 0.f;
#pragma unroll
        for (int i = 0; i < 8; i++) {
            float4 w = wr[lane + 32 * i];
            s = fmaf(xf[i].x, w.x, s);
            s = fmaf(xf[i].y, w.y, s);
            s = fmaf(xf[i].z, w.z, s);
            s = fmaf(xf[i].w, w.w, s);
        }
#pragma unroll
        for (int o = 16; o > 0; o >>= 1) s += __shfl_xor_sync(0xffffffffu, s, o);
        p[e] = s;
    }

    if (lane == 0) {
        int i0 = 0;
#pragma unroll
        for (int e = 1; e < NEXP; e++) if (p[e] > p[i0]) i0 = e;
        int i1 = (i0 == 0) ? 1 : 0;
#pragma unroll
        for (int e = 0; e < NEXP; e++) if (e != i0 && p[e] > p[i1]) i1 = e;

        float mx = p[i0];
        float den = 0.f, pe[NEXP];
#pragma unroll
        for (int e = 0; e < NEXP; e++) { pe[e] = expf(p[e] - mx); den += pe[e]; }
        d_tokeid[2 * gw]     = i0;
        d_tokeid[2 * gw + 1] = i1;
        d_tokw[2 * gw]       = pe[i0] / den;
        d_tokw[2 * gw + 1]   = pe[i1] / den;
        atomicAdd(&d_cnt[i0], 1);
        atomicAdd(&d_cnt[i1], 1);
    }
}

__global__ void k_offsets() {
    if (threadIdx.x == 0) {
        int s = 0;
        for (int e = 0; e < NEXP; e++) { d_off[e] = s; s += d_cnt[e]; }
    }
    if (threadIdx.x < NEXP) d_cur[threadIdx.x] = 0;
}

__global__ void k_assign() {
    int t = blockIdx.x * blockDim.x + threadIdx.x;
    if (t >= T_TOK) return;
#pragma unroll
    for (int k = 0; k < TOPK; k++) {
        int e   = d_tokeid[2 * t + k];
        int pos = atomicAdd(&d_cur[e], 1);
        int slot = d_off[e] + pos;
        d_rowidx[slot]       = t;
        d_tokslot[2 * t + k] = slot;
    }
}

// ======================= GEMM1: h = Xg @ W^T (bf16 3-term) ====================
// BM=128, BN=64, BK=32, 256 threads (8 warps 4x2), warp tile 32x32.
// smem (bf16 units per buffer): Ah[128][40]@0, Al@5120, Bh[64][40]@10240, Bl@12800
#define G1_BUF 15360                   /* units */
#define G1_BUFB (G1_BUF * 2)           /* bytes */
#define G1_AH 0
#define G1_AL 5120
#define G1_BH 10240
#define G1_BL 12800

__global__ __launch_bounds__(256) void k_gemm1(const float* __restrict__ X,
                                               const float* __restrict__ Bw,
                                               int which) {
    const int e     = blockIdx.z;
    const int cnt   = d_cnt[e];
    const int mbase = blockIdx.y * 128;
    if (mbase >= cnt) return;
    const int n0       = blockIdx.x * 64;
    const int slotbase = d_off[e] + mbase;
    float* __restrict__ outp = which ? d_h2 : d_h1;   // resolved in DEVICE code

    extern __shared__ __nv_bfloat16 sm[];
    __shared__ int rs[128];

    const int tid  = threadIdx.x;
    const int lane = tid & 31;
    const int warp = tid >> 5;
    const int g    = lane >> 2;
    const int tg   = lane & 3;
    const int wm   = warp >> 1;      // 0..3 -> m offset wm*32
    const int wn   = warp & 1;       // 0..1 -> n offset wn*32

    if (tid < 128) rs[tid] = d_rowidx[min(slotbase + tid, NSLOT - 1)];
    __syncthreads();

    const float* Be = Bw + (size_t)e * FFN * HID;

    // loader mapping
    const int arow = tid >> 1, akq = (tid & 1) * 4;   // 4 float4 each
    const int brow = tid >> 2, bkq = (tid & 3) * 2;   // 2 float4 each
    const size_t arow_g = (size_t)rs[arow] * HID;
    const size_t brow_g = (size_t)(n0 + brow) * HID;

    // ldmatrix per-lane base byte offsets
    const uint32_t usm = s2u(sm);
    const uint32_t aAddr = usm + (uint32_t)((wm * 32 + (lane & 15)) * 40 + ((lane >> 4) << 3)) * 2;
    const uint32_t bAddr = usm + (uint32_t)(G1_BH * 2) +
                           (uint32_t)((wn * 32 + ((lane >> 4) << 3) + (lane & 7)) * 40 + (lane & 8)) * 2;

    float acc[2][4][4];
#pragma unroll
    for (int i = 0; i < 2; i++)
#pragma unroll
        for (int j = 0; j < 4; j++)
#pragma unroll
            for (int c = 0; c < 4; c++) acc[i][j][c] = 0.f;

    float4 va[4], vb[2];

    auto ldglob = [&](int k0) {
#pragma unroll
        for (int j = 0; j < 4; j++)
            va[j] = *(const float4*)(X + arow_g + k0 + (akq + j) * 4);
#pragma unroll
        for (int j = 0; j < 2; j++)
            vb[j] = *(const float4*)(Be + brow_g + k0 + (bkq + j) * 4);
    };
    auto stsm = [&](int buf) {
        __nv_bfloat16* base = sm + buf * G1_BUF;
#pragma unroll
        for (int j = 0; j < 4; j++) {
            uint2 h, l;
            cvt4(va[j], h, l);
            int u = arow * 40 + (akq + j) * 4;
            *(uint2*)(base + G1_AH + u) = h;
            *(uint2*)(base + G1_AL + u) = l;
        }
#pragma unroll
        for (int j = 0; j < 2; j++) {
            uint2 h, l;
            cvt4(vb[j], h, l);
            int u = brow * 40 + (bkq + j) * 4;
            *(uint2*)(base + G1_BH + u) = h;
            *(uint2*)(base + G1_BL + u) = l;
        }
    };

    const int KT = HID / 32;   // 32 chunks
    ldglob(0);
    stsm(0);
    __syncthreads();

    for (int kt = 0; kt < KT; kt++) {
        const int buf = kt & 1;
        if (kt + 1 < KT) ldglob((kt + 1) * 32);

        const uint32_t bufB = (uint32_t)buf * G1_BUFB;
#pragma unroll
        for (int ks = 0; ks < 2; ks++) {
            const uint32_t ko = ks * 32;   // 16 elems = 32B
            uint32_t ah[2][4], al[2][4], bh[4][2], bl[4][2];
#pragma unroll
            for (int mt = 0; mt < 2; mt++) {
                uint32_t ad = aAddr + bufB + mt * 1280u + ko;
                LDSM_X4(ah[mt][0], ah[mt][1], ah[mt][2], ah[mt][3], ad);
                LDSM_X4(al[mt][0], al[mt][1], al[mt][2], al[mt][3], ad + 10240u);
            }
#pragma unroll
            for (int ng = 0; ng < 2; ng++) {
                uint32_t bd = bAddr + bufB + ng * 1280u + ko;
                LDSM_X4(bh[2 * ng][0], bh[2 * ng][1], bh[2 * ng + 1][0], bh[2 * ng + 1][1], bd);
                LDSM_X4(bl[2 * ng][0], bl[2 * ng][1], bl[2 * ng + 1][0], bl[2 * ng + 1][1], bd + 5120u);
            }
#pragma unroll
            for (int mt = 0; mt < 2; mt++)
#pragma unroll
                for (int nt = 0; nt < 4; nt++) {
                    MMA16816(acc[mt][nt], ah[mt], bl[nt][0], bl[nt][1]);
                    MMA16816(acc[mt][nt], al[mt], bh[nt][0], bh[nt][1]);
                    MMA16816(acc[mt][nt], ah[mt], bh[nt][0], bh[nt][1]);
                }
        }
        if (kt + 1 < KT) stsm(buf ^ 1);
        __syncthreads();
    }

    const int mrem = cnt - mbase;
#pragma unroll
    for (int mt = 0; mt < 2; mt++) {
        int m0 = wm * 32 + mt * 16 + g;
        if (m0 < mrem) {
            float* orow = outp + (size_t)(slotbase + m0) * FFN + n0;
#pragma unroll
            for (int nt = 0; nt < 4; nt++)
                *(float2*)(orow + wn * 32 + nt * 8 + 2 * tg) =
                    make_float2(acc[mt][nt][0], acc[mt][nt][1]);
        }
        if (m0 + 8 < mrem) {
            float* orow = outp + (size_t)(slotbase + m0 + 8) * FFN + n0;
#pragma unroll
            for (int nt = 0; nt < 4; nt++)
                *(float2*)(orow + wn * 32 + nt * 8 + 2 * tg) =
                    make_float2(acc[mt][nt][2], acc[mt][nt][3]);
        }
    }
}

// ---------------- GLU: g = gelu(h1)*h2 -> bf16 hi/lo planes ----------------
__global__ void k_glu() {
    size_t i = (size_t)blockIdx.x * blockDim.x + threadIdx.x;
    const size_t n4 = (size_t)NSLOT * FFN / 4;
    if (i >= n4) return;
    float4 a = ((const float4*)d_h1)[i];
    float4 b = ((const float4*)d_h2)[i];
    float4 gv;
    gv.x = gelu_tanh(a.x) * b.x;
    gv.y = gelu_tanh(a.y) * b.y;
    gv.z = gelu_tanh(a.z) * b.z;
    gv.w = gelu_tanh(a.w) * b.w;
    uint2 h, l;
    cvt4(gv, h, l);
    ((uint2*)d_gh)[i] = h;
    ((uint2*)d_gl)[i] = l;
}

// ======================= GEMM2: y = g @ W2 (bf16 3-term) =====================
// A: pre-split g planes (pure copy). B: w2 [F][H] k-strided -> smem [k32][n64+pad],
// fragments via ldmatrix.trans.
// smem units/buffer: Ah[128][40]@0, Al@5120, Bh[32][72]@10240, Bl@12544
#define G2_BUF 14848
#define G2_BUFB (G2_BUF * 2)
#define G2_AH 0
#define G2_AL 5120
#define G2_BH 10240
#define G2_BL 12544

__global__ __launch_bounds__(256) void k_gemm2(const float* __restrict__ W2) {
    const int e     = blockIdx.z;
    const int cnt   = d_cnt[e];
    const int mbase = blockIdx.y * 128;
    if (mbase >= cnt) return;
    const int n0       = blockIdx.x * 64;
    const int slotbase = d_off[e] + mbase;

    extern __shared__ __nv_bfloat16 sm[];

    const int tid  = threadIdx.x;
    const int lane = tid & 31;
    const int warp = tid >> 5;
    const int g    = lane >> 2;
    const int tg   = lane & 3;
    const int wm   = warp >> 1;
    const int wn   = warp & 1;

    const float* Be = W2 + (size_t)e * FFN * HID;

    const int arow = tid >> 1, aseg = (tid & 1) * 4;     // 4 x uint2 per plane
    const int bkrow = tid >> 3, bnq = (tid & 7) * 2;     // 2 float4
    const size_t arow_g = (size_t)min(slotbase + arow, NSLOT - 1) * FFN;

    const uint32_t usm = s2u(sm);
    const uint32_t aAddr = usm + (uint32_t)((wm * 32 + (lane & 15)) * 40 + ((lane >> 4) << 3)) * 2;
    const uint32_t bAddr = usm + (uint32_t)(G2_BH * 2) +
                           (uint32_t)(((lane & 8) + (lane & 7)) * 72 + wn * 32 + ((lane >> 4) << 3)) * 2;

    float acc[2][4][4];
#pragma unroll
    for (int i = 0; i < 2; i++)
#pragma unroll
        for (int j = 0; j < 4; j++)
#pragma unroll
            for (int c = 0; c < 4; c++) acc[i][j][c] = 0.f;

    uint2 vah[4], val[4];
    float4 vb[2];

    auto ldglob = [&](int k0) {
#pragma unroll
        for (int j = 0; j < 4; j++) {
            vah[j] = *(const uint2*)(d_gh + arow_g + k0 + (aseg + j) * 4);
            val[j] = *(const uint2*)(d_gl + arow_g + k0 + (aseg + j) * 4);
        }
#pragma unroll
        for (int j = 0; j < 2; j++)
            vb[j] = *(const float4*)(Be + (size_t)(k0 + bkrow) * HID + n0 + (bnq + j) * 4);
    };
    auto stsm = [&](int buf) {
        __nv_bfloat16* base = sm + buf * G2_BUF;
#pragma unroll
        for (int j = 0; j < 4; j++) {
            int u = arow * 40 + (aseg + j) * 4;
            *(uint2*)(base + G2_AH + u) = vah[j];
            *(uint2*)(base + G2_AL + u) = val[j];
        }
#pragma unroll
        for (int j = 0; j < 2; j++) {
            uint2 h, l;
            cvt4(vb[j], h, l);
            int u = bkrow * 72 + (bnq + j) * 4;
            *(uint2*)(base + G2_BH + u) = h;
            *(uint2*)(base + G2_BL + u) = l;
        }
    };

    const int KT = FFN / 32;   // 128 chunks
    ldglob(0);
    stsm(0);
    __syncthreads();

    for (int kt = 0; kt < KT; kt++) {
        const int buf = kt & 1;
        if (kt + 1 < KT) ldglob((kt + 1) * 32);

        const uint32_t bufB = (uint32_t)buf * G2_BUFB;
#pragma unroll
        for (int ks = 0; ks < 2; ks++) {
            uint32_t ah[2][4], al[2][4], bh[4][2], bl[4][2];
#pragma unroll
            for (int mt = 0; mt < 2; mt++) {
                uint32_t ad = aAddr + bufB + mt * 1280u + ks * 32u;
                LDSM_X4(ah[mt][0], ah[mt][1], ah[mt][2], ah[mt][3], ad);
                LDSM_X4(al[mt][0], al[mt][1], al[mt][2], al[mt][3], ad + 10240u);
            }
#pragma unroll
            for (int ng = 0; ng < 2; ng++) {
                uint32_t bd = bAddr + bufB + ng * 32u + ks * 2304u;
                LDSM_X4T(bh[2 * ng][0], bh[2 * ng][1], bh[2 * ng + 1][0], bh[2 * ng + 1][1], bd);
                LDSM_X4T(bl[2 * ng][0], bl[2 * ng][1], bl[2 * ng + 1][0], bl[2 * ng + 1][1], bd + 4608u);
            }
#pragma unroll
            for (int mt = 0; mt < 2; mt++)
#pragma unroll
                for (int nt = 0; nt < 4; nt++) {
                    MMA16816(acc[mt][nt], ah[mt], bl[nt][0], bl[nt][1]);
                    MMA16816(acc[mt][nt], al[mt], bh[nt][0], bh[nt][1]);
                    MMA16816(acc[mt][nt], ah[mt], bh[nt][0], bh[nt][1]);
                }
        }
        if (kt + 1 < KT) stsm(buf ^ 1);
        __syncthreads();
    }

    const int mrem = cnt - mbase;
#pragma unroll
    for (int mt = 0; mt < 2; mt++) {
        int m0 = wm * 32 + mt * 16 + g;
        if (m0 < mrem) {
            float* orow = d_y + (size_t)(slotbase + m0) * HID + n0;
#pragma unroll
            for (int nt = 0; nt < 4; nt++)
                *(float2*)(orow + wn * 32 + nt * 8 + 2 * tg) =
                    make_float2(acc[mt][nt][0], acc[mt][nt][1]);
        }
        if (m0 + 8 < mrem) {
            float* orow = d_y + (size_t)(slotbase + m0 + 8) * HID + n0;
#pragma unroll
            for (int nt = 0; nt < 4; nt++)
                *(float2*)(orow + wn * 32 + nt * 8 + 2 * tg) =
                    make_float2(acc[mt][nt][2], acc[mt][nt][3]);
        }
    }
}

// ---------------- combine: out[t] = w0*y[s0] + w1*y[s1] ----------------
__global__ void k_combine(float* __restrict__ out) {
    int idx = blockIdx.x * blockDim.x + threadIdx.x;
    const int n4 = T_TOK * (HID / 4);
    if (idx >= n4) return;
    int t = idx / (HID / 4);
    int h = idx - t * (HID / 4);
    int s0 = d_tokslot[2 * t];
    int s1 = d_tokslot[2 * t + 1];
    float w0 = d_tokw[2 * t];
    float w1 = d_tokw[2 * t + 1];
    float4 y0 = ((const float4*)d_y)[(size_t)s0 * (HID / 4) + h];
    float4 y1 = ((const float4*)d_y)[(size_t)s1 * (HID / 4) + h];
    float4 o;
    o.x = w0 * y0.x + w1 * y1.x;
    o.y = w0 * y0.y + w1 * y1.y;
    o.z = w0 * y0.z + w1 * y1.z;
    o.w = w0 * y0.w + w1 * y1.w;
    ((float4*)out)[idx] = o;
}

// ---------------- launch ----------------
extern "C" void kernel_launch(void* const* d_in, const int* in_sizes, int n_in,
                              void* d_out, int out_size) {
    (void)in_sizes; (void)n_in; (void)out_size;
    const float* x  = (const float*)d_in[0];
    const float* rw = (const float*)d_in[1];
    const float* w1 = (const float*)d_in[2];
    const float* v1 = (const float*)d_in[3];
    const float* w2 = (const float*)d_in[4];
    float* out = (float*)d_out;

    const int SMEM1 = 2 * G1_BUFB;  // 61440 B
    const int SMEM2 = 2 * G2_BUFB;  // 59392 B
    cudaFuncSetAttribute(k_gemm1, cudaFuncAttributeMaxDynamicSharedMemorySize, SMEM1);
    cudaFuncSetAttribute(k_gemm2, cudaFuncAttributeMaxDynamicSharedMemorySize, SMEM2);

    k_init<<<1, 32>>>();
    k_router<<<T_TOK / 4, 128>>>(x, rw);
    k_offsets<<<1, 32>>>();
    k_assign<<<T_TOK / 256, 256>>>();

    dim3 g1(FFN / 64, 32, NEXP);
    k_gemm1<<<g1, 256, SMEM1>>>(x, w1, 0);
    k_gemm1<<<g1, 256, SMEM1>>>(x, v1, 1);

    k_glu<<<(NSLOT * (FFN / 4)) / 256, 256>>>();

    dim3 g2(HID / 64, 32, NEXP);
    k_gemm2<<<g2, 256, SMEM2>>>(w2);

    k_combine<<<(T_TOK * (HID / 4)) / 256, 256>>>(out);
}

// round 11
// speedup vs baseline: 1.5095x; 1.1852x over previous
#include <cuda_runtime.h>
#include <cuda_bf16.h>
#include <cstdint>

#define T_TOK 4096
#define HID   1024
#define NEXP  8
#define FFN   4096
#define TOPK  2
#define NSLOT (T_TOK*TOPK)   /* 8192, fixed */

// ---------------- static scratch ----------------
__device__ __nv_bfloat16 d_gh[(size_t)NSLOT * FFN];
__device__ __nv_bfloat16 d_gl[(size_t)NSLOT * FFN];
__device__ float d_y[(size_t)NSLOT * HID];
__device__ int   d_cnt[NEXP];
__device__ int   d_off[NEXP];
__device__ int   d_cur[NEXP];
__device__ int   d_rowidx[NSLOT];
__device__ int   d_tokeid[T_TOK * TOPK];
__device__ int   d_tokslot[T_TOK * TOPK];
__device__ float d_tokw[T_TOK * TOPK];

// ---------------- helpers ----------------
__device__ __forceinline__ uint32_t s2u(const void* p) {
    uint32_t r;
    asm("{ .reg .u64 t; cvta.to.shared.u64 t, %1; cvt.u32.u64 %0, t; }" : "=r"(r) : "l"(p));
    return r;
}

#define LDSM_X4(r0, r1, r2, r3, addr) \
    asm volatile("ldmatrix.sync.aligned.m8n8.x4.shared.b16 {%0,%1,%2,%3}, [%4];" \
                 : "=r"(r0), "=r"(r1), "=r"(r2), "=r"(r3) : "r"(addr))

#define LDSM_X4T(r0, r1, r2, r3, addr) \
    asm volatile("ldmatrix.sync.aligned.m8n8.x4.trans.shared.b16 {%0,%1,%2,%3}, [%4];" \
                 : "=r"(r0), "=r"(r1), "=r"(r2), "=r"(r3) : "r"(addr))

#define MMA16816(c, a, b0, b1) \
    asm volatile("mma.sync.aligned.m16n8k16.row.col.f32.bf16.bf16.f32 " \
                 "{%0,%1,%2,%3},{%4,%5,%6,%7},{%8,%9},{%0,%1,%2,%3};" \
                 : "+f"((c)[0]), "+f"((c)[1]), "+f"((c)[2]), "+f"((c)[3]) \
                 : "r"((a)[0]), "r"((a)[1]), "r"((a)[2]), "r"((a)[3]), "r"(b0), "r"(b1))

__device__ __forceinline__ void cpa16(uint32_t saddr, const void* g) {
    asm volatile("cp.async.cg.shared.global [%0], [%1], 16;" :: "r"(saddr), "l"(g));
}

__device__ __forceinline__ float gelu_tanh(float x) {
    float x3 = x * x * x;
    float t = tanhf(0.7978845608028654f * (x + 0.044715f * x3));
    return 0.5f * x * (1.0f + t);
}

__device__ __forceinline__ void cvt4(float4 v, uint2& h, uint2& l) {
    __nv_bfloat16 hx = __float2bfloat16(v.x), hy = __float2bfloat16(v.y);
    __nv_bfloat16 hz = __float2bfloat16(v.z), hw = __float2bfloat16(v.w);
    __nv_bfloat16 lx = __float2bfloat16(v.x - __bfloat162float(hx));
    __nv_bfloat16 ly = __float2bfloat16(v.y - __bfloat162float(hy));
    __nv_bfloat16 lz = __float2bfloat16(v.z - __bfloat162float(hz));
    __nv_bfloat16 lw = __float2bfloat16(v.w - __bfloat162float(hw));
    h.x = ((uint32_t)__bfloat16_as_ushort(hy) << 16) | __bfloat16_as_ushort(hx);
    h.y = ((uint32_t)__bfloat16_as_ushort(hw) << 16) | __bfloat16_as_ushort(hz);
    l.x = ((uint32_t)__bfloat16_as_ushort(ly) << 16) | __bfloat16_as_ushort(lx);
    l.y = ((uint32_t)__bfloat16_as_ushort(lw) << 16) | __bfloat16_as_ushort(lz);
}

// ---------------- routing kernels ----------------
__global__ void k_init() {
    if (threadIdx.x < NEXP) d_cnt[threadIdx.x] = 0;
}

__global__ void k_router(const float* __restrict__ x, const float* __restrict__ rw) {
    int gw   = (blockIdx.x * blockDim.x + threadIdx.x) >> 5;
    int lane = threadIdx.x & 31;
    if (gw >= T_TOK) return;

    const float4* xr = reinterpret_cast<const float4*>(x + (size_t)gw * HID);
    float4 xf[8];
#pragma unroll
    for (int i = 0; i < 8; i++) xf[i] = xr[lane + 32 * i];

    float p[NEXP];
#pragma unroll
    for (int e = 0; e < NEXP; e++) {
        const float4* wr = reinterpret_cast<const float4*>(rw + (size_t)e * HID);
        float s = 0.f;
#pragma unroll
        for (int i = 0; i < 8; i++) {
            float4 w = wr[lane + 32 * i];
            s = fmaf(xf[i].x, w.x, s);
            s = fmaf(xf[i].y, w.y, s);
            s = fmaf(xf[i].z, w.z, s);
            s = fmaf(xf[i].w, w.w, s);
        }
#pragma unroll
        for (int o = 16; o > 0; o >>= 1) s += __shfl_xor_sync(0xffffffffu, s, o);
        p[e] = s;
    }

    if (lane == 0) {
        int i0 = 0;
#pragma unroll
        for (int e = 1; e < NEXP; e++) if (p[e] > p[i0]) i0 = e;
        int i1 = (i0 == 0) ? 1 : 0;
#pragma unroll
        for (int e = 0; e < NEXP; e++) if (e != i0 && p[e] > p[i1]) i1 = e;

        float mx = p[i0];
        float den = 0.f, pe[NEXP];
#pragma unroll
        for (int e = 0; e < NEXP; e++) { pe[e] = expf(p[e] - mx); den += pe[e]; }
        d_tokeid[2 * gw]     = i0;
        d_tokeid[2 * gw + 1] = i1;
        d_tokw[2 * gw]       = pe[i0] / den;
        d_tokw[2 * gw + 1]   = pe[i1] / den;
        atomicAdd(&d_cnt[i0], 1);
        atomicAdd(&d_cnt[i1], 1);
    }
}

__global__ void k_offsets() {
    if (threadIdx.x == 0) {
        int s = 0;
        for (int e = 0; e < NEXP; e++) { d_off[e] = s; s += d_cnt[e]; }
    }
    if (threadIdx.x < NEXP) d_cur[threadIdx.x] = 0;
}

__global__ void k_assign() {
    int t = blockIdx.x * blockDim.x + threadIdx.x;
    if (t >= T_TOK) return;
#pragma unroll
    for (int k = 0; k < TOPK; k++) {
        int e   = d_tokeid[2 * t + k];
        int pos = atomicAdd(&d_cur[e], 1);
        int slot = d_off[e] + pos;
        d_rowidx[slot]       = t;
        d_tokslot[2 * t + k] = slot;
    }
}

// ============ GEMM1 fused: h1,h2 tiles + GLU -> g planes (bf16 3-term) ========
// BM=128, B tile = [w1 cols n0..n0+63 ; v1 cols n0..n0+63] (128 rows), BK=64.
// 512 threads, 16 warps (4m x 4n), warp tile 32x32.
// smem units (bf16), pitch 72: Ah@0, Al@9216, Bh@18432, Bl@27648; buf=36864u.
#define P1      72
#define G1_AL   9216
#define G1_BH   18432
#define G1_BUFU 36864
#define G1_BUFB 73728

__global__ __launch_bounds__(512) void k_gemm1f(const float* __restrict__ X,
                                                const float* __restrict__ W1,
                                                const float* __restrict__ V1) {
    const int e     = blockIdx.z;
    const int cnt   = d_cnt[e];
    const int mbase = blockIdx.y * 128;
    if (mbase >= cnt) return;
    const int n0       = blockIdx.x * 64;
    const int slotbase = d_off[e] + mbase;

    extern __shared__ __nv_bfloat16 sm[];
    __shared__ int rs[128];

    const int tid  = threadIdx.x;
    const int lane = tid & 31;
    const int warp = tid >> 5;
    const int g    = lane >> 2;
    const int tg   = lane & 3;
    const int wm   = warp >> 2;      // 0..3
    const int wnq  = warp & 3;       // 0..3: 0,1->h1 cols; 2,3->h2 cols

    if (tid < 128) rs[tid] = d_rowidx[min(slotbase + tid, NSLOT - 1)];
    __syncthreads();

    // loaders: 4 threads per row, 4 float4 each (BK=64)
    const int arow = tid >> 2;
    const int aq   = (tid & 3) * 4;       // float4 index base
    const size_t ag = (size_t)rs[arow] * HID;
    const float* bp = (arow < 64)
        ? (W1 + ((size_t)e * FFN + n0 + arow) * HID)
        : (V1 + ((size_t)e * FFN + n0 + arow - 64) * HID);

    const uint32_t usm = s2u(sm);
    const uint32_t aAddr = usm + (uint32_t)((wm * 32 + (lane & 15)) * P1 + ((lane >> 4) << 3)) * 2;
    const uint32_t bAddr = usm + (uint32_t)(G1_BH * 2) +
                           (uint32_t)((wnq * 32 + ((lane >> 4) << 3) + (lane & 7)) * P1 + (lane & 8)) * 2;

    float acc[2][4][4];
#pragma unroll
    for (int i = 0; i < 2; i++)
#pragma unroll
        for (int j = 0; j < 4; j++)
#pragma unroll
            for (int c = 0; c < 4; c++) acc[i][j][c] = 0.f;

    float4 va[4], vb[4];
    auto ldglob = [&](int k0) {
#pragma unroll
        for (int j = 0; j < 4; j++) va[j] = *(const float4*)(X + ag + k0 + (aq + j) * 4);
#pragma unroll
        for (int j = 0; j < 4; j++) vb[j] = *(const float4*)(bp + k0 + (aq + j) * 4);
    };
    auto stsm = [&](int buf) {
        __nv_bfloat16* base = sm + buf * G1_BUFU;
#pragma unroll
        for (int j = 0; j < 4; j++) {
            uint2 h, l;
            cvt4(va[j], h, l);
            int u = arow * P1 + (aq + j) * 4;
            *(uint2*)(base + u) = h;
            *(uint2*)(base + G1_AL + u) = l;
        }
#pragma unroll
        for (int j = 0; j < 4; j++) {
            uint2 h, l;
            cvt4(vb[j], h, l);
            int u = arow * P1 + (aq + j) * 4;
            *(uint2*)(base + G1_BH + u) = h;
            *(uint2*)(base + G1_BH + 9216 + u) = l;
        }
    };

    const int KT = HID / 64;  // 16
    ldglob(0);
    stsm(0);
    __syncthreads();

    for (int kt = 0; kt < KT; kt++) {
        const int buf = kt & 1;
        if (kt + 1 < KT) ldglob((kt + 1) * 64);

        const uint32_t bufB = (uint32_t)buf * G1_BUFB;
#pragma unroll
        for (int ks = 0; ks < 4; ks++) {
            const uint32_t ko = ks * 32u;
            uint32_t ah[2][4], al[2][4], bh[4][2], bl[4][2];
#pragma unroll
            for (int mt = 0; mt < 2; mt++) {
                uint32_t ad = aAddr + bufB + mt * 2304u + ko;
                LDSM_X4(ah[mt][0], ah[mt][1], ah[mt][2], ah[mt][3], ad);
                LDSM_X4(al[mt][0], al[mt][1], al[mt][2], al[mt][3], ad + 18432u);
            }
#pragma unroll
            for (int ng = 0; ng < 2; ng++) {
                uint32_t bd = bAddr + bufB + ng * 2304u + ko;
                LDSM_X4(bh[2 * ng][0], bh[2 * ng][1], bh[2 * ng + 1][0], bh[2 * ng + 1][1], bd);
                LDSM_X4(bl[2 * ng][0], bl[2 * ng][1], bl[2 * ng + 1][0], bl[2 * ng + 1][1], bd + 18432u);
            }
#pragma unroll
            for (int mt = 0; mt < 2; mt++)
#pragma unroll
                for (int nt = 0; nt < 4; nt++) {
                    MMA16816(acc[mt][nt], ah[mt], bl[nt][0], bl[nt][1]);
                    MMA16816(acc[mt][nt], al[mt], bh[nt][0], bh[nt][1]);
                    MMA16816(acc[mt][nt], ah[mt], bh[nt][0], bh[nt][1]);
                }
        }
        if (kt + 1 < KT) stsm(buf ^ 1);
        __syncthreads();
    }

    // ---- epilogue: exchange h1/h2 via smem, GLU, split to bf16 planes ----
    const int HP = 66;
    float* hsc = (float*)sm;                       // [2][128][66] = 67584 B
    float* myh = hsc + (wnq >> 1) * 128 * HP;
    const int ncb = (wnq & 1) * 32;
#pragma unroll
    for (int mt = 0; mt < 2; mt++)
#pragma unroll
        for (int half = 0; half < 2; half++) {
            int m = wm * 32 + mt * 16 + g + half * 8;
#pragma unroll
            for (int nt = 0; nt < 4; nt++) {
                int c = ncb + nt * 8 + 2 * tg;
                *(float2*)(myh + m * HP + c) =
                    make_float2(acc[mt][nt][half * 2], acc[mt][nt][half * 2 + 1]);
            }
        }
    __syncthreads();

    const int mrem = cnt - mbase;
    const float* h1s = hsc;
    const float* h2s = hsc + 128 * HP;
    for (int idx = tid; idx < 128 * 32; idx += 512) {
        int r = idx >> 5, cu = idx & 31;
        if (r < mrem) {
            int c = 2 * cu;
            float2 a = *(const float2*)(h1s + r * HP + c);
            float2 b = *(const float2*)(h2s + r * HP + c);
            float g0 = gelu_tanh(a.x) * b.x;
            float g1 = gelu_tanh(a.y) * b.y;
            __nv_bfloat16 h0 = __float2bfloat16(g0), h1 = __float2bfloat16(g1);
            __nv_bfloat16 l0 = __float2bfloat16(g0 - __bfloat162float(h0));
            __nv_bfloat16 l1 = __float2bfloat16(g1 - __bfloat162float(h1));
            uint32_t hp = ((uint32_t)__bfloat16_as_ushort(h1) << 16) | __bfloat16_as_ushort(h0);
            uint32_t lp = ((uint32_t)__bfloat16_as_ushort(l1) << 16) | __bfloat16_as_ushort(l0);
            size_t base = (size_t)(slotbase + r) * FFN + n0 + c;
            *(uint32_t*)(d_gh + base) = hp;
            *(uint32_t*)(d_gl + base) = lp;
        }
    }
}

// ============ GEMM2: y = g @ W2 (bf16 3-term, BK=64, cp.async A) =============
// 256 threads, 8 warps (4m x 2n), warp tile 32x32, BM=128 BN=64.
// smem units pitch 72: Ah@0, Al@9216, Bh@18432 (64 krows), Bl@23040; buf=27648u.
#define P2      72
#define G2_AL   9216
#define G2_BH   18432
#define G2_BUFU 27648
#define G2_BUFB 55296

__global__ __launch_bounds__(256) void k_gemm2(const float* __restrict__ W2) {
    const int e     = blockIdx.z;
    const int cnt   = d_cnt[e];
    const int mbase = blockIdx.y * 128;
    if (mbase >= cnt) return;
    const int n0       = blockIdx.x * 64;
    const int slotbase = d_off[e] + mbase;

    extern __shared__ __nv_bfloat16 sm[];

    const int tid  = threadIdx.x;
    const int lane = tid & 31;
    const int warp = tid >> 5;
    const int g    = lane >> 2;
    const int tg   = lane & 3;
    const int wm   = warp >> 1;
    const int wn   = warp & 1;

    const float* Be = W2 + (size_t)e * FFN * HID;
    const uint32_t usm = s2u(sm);

    // cp.async A mapping: 2048 16B-chunks (128 rows x 8 chunks x 2 planes), 8/thread
    const __nv_bfloat16* asrc[8];
    uint32_t adst[8];
#pragma unroll
    for (int jj = 0; jj < 8; jj++) {
        int idx   = tid + 256 * jj;
        int plane = idx >> 10;
        int row   = (idx >> 3) & 127;
        int cc    = idx & 7;
        const __nv_bfloat16* srcb = plane ? d_gl : d_gh;
        asrc[jj] = srcb + (size_t)min(slotbase + row, NSLOT - 1) * FFN + cc * 8;
        adst[jj] = (uint32_t)(plane * G2_AL + row * P2 + cc * 8) * 2;
    }

    // B loader: 4 threads/row over 64 krows, 4 float4 each
    const int bkrow = tid >> 2;
    const int bq    = (tid & 3) * 4;

    const uint32_t aAddr = usm + (uint32_t)((wm * 32 + (lane & 15)) * P2 + ((lane >> 4) << 3)) * 2;
    const uint32_t bAddr = usm + (uint32_t)(G2_BH * 2) +
                           (uint32_t)(((lane & 8) + (lane & 7)) * P2 + wn * 32 + ((lane >> 4) << 3)) * 2;

    float acc[2][4][4];
#pragma unroll
    for (int i = 0; i < 2; i++)
#pragma unroll
        for (int j = 0; j < 4; j++)
#pragma unroll
            for (int c = 0; c < 4; c++) acc[i][j][c] = 0.f;

    float4 vb[4];
    auto cpA = [&](int k0, int buf) {
        uint32_t b = usm + buf * (uint32_t)G2_BUFB;
#pragma unroll
        for (int jj = 0; jj < 8; jj++) cpa16(b + adst[jj], asrc[jj] + k0);
        asm volatile("cp.async.commit_group;");
    };
    auto ldB = [&](int k0) {
#pragma unroll
        for (int j = 0; j < 4; j++)
            vb[j] = *(const float4*)(Be + (size_t)(k0 + bkrow) * HID + n0 + (bq + j) * 4);
    };
    auto stB = [&](int buf) {
        __nv_bfloat16* base = sm + buf * G2_BUFU;
#pragma unroll
        for (int j = 0; j < 4; j++) {
            uint2 h, l;
            cvt4(vb[j], h, l);
            int u = bkrow * P2 + (bq + j) * 4;
            *(uint2*)(base + G2_BH + u) = h;
            *(uint2*)(base + G2_BH + 4608 + u) = l;
        }
    };

    const int KT = FFN / 64;  // 64
    cpA(0, 0);
    ldB(0);
    stB(0);
    asm volatile("cp.async.wait_group 0;");
    __syncthreads();

    for (int kt = 0; kt < KT; kt++) {
        const int buf = kt & 1;
        if (kt + 1 < KT) {
            cpA((kt + 1) * 64, buf ^ 1);
            ldB((kt + 1) * 64);
        }

        const uint32_t bufB = (uint32_t)buf * G2_BUFB;
#pragma unroll
        for (int ks = 0; ks < 4; ks++) {
            uint32_t ah[2][4], al[2][4], bh[4][2], bl[4][2];
#pragma unroll
            for (int mt = 0; mt < 2; mt++) {
                uint32_t ad = aAddr + bufB + mt * 2304u + ks * 32u;
                LDSM_X4(ah[mt][0], ah[mt][1], ah[mt][2], ah[mt][3], ad);
                LDSM_X4(al[mt][0], al[mt][1], al[mt][2], al[mt][3], ad + 18432u);
            }
#pragma unroll
            for (int ng = 0; ng < 2; ng++) {
                uint32_t bd = bAddr + bufB + ng * 32u + ks * 2304u;
                LDSM_X4T(bh[2 * ng][0], bh[2 * ng][1], bh[2 * ng + 1][0], bh[2 * ng + 1][1], bd);
                LDSM_X4T(bl[2 * ng][0], bl[2 * ng][1], bl[2 * ng + 1][0], bl[2 * ng + 1][1], bd + 9216u);
            }
#pragma unroll
            for (int mt = 0; mt < 2; mt++)
#pragma unroll
                for (int nt = 0; nt < 4; nt++) {
                    MMA16816(acc[mt][nt], ah[mt], bl[nt][0], bl[nt][1]);
                    MMA16816(acc[mt][nt], al[mt], bh[nt][0], bh[nt][1]);
                    MMA16816(acc[mt][nt], ah[mt], bh[nt][0], bh[nt][1]);
                }
        }
        if (kt + 1 < KT) stB(buf ^ 1);
        asm volatile("cp.async.wait_group 0;");
        __syncthreads();
    }

    const int mrem = cnt - mbase;
#pragma unroll
    for (int mt = 0; mt < 2; mt++) {
        int m0 = wm * 32 + mt * 16 + g;
        if (m0 < mrem) {
            float* orow = d_y + (size_t)(slotbase + m0) * HID + n0;
#pragma unroll
            for (int nt = 0; nt < 4; nt++)
                *(float2*)(orow + wn * 32 + nt * 8 + 2 * tg) =
                    make_float2(acc[mt][nt][0], acc[mt][nt][1]);
        }
        if (m0 + 8 < mrem) {
            float* orow = d_y + (size_t)(slotbase + m0 + 8) * HID + n0;
#pragma unroll
            for (int nt = 0; nt < 4; nt++)
                *(float2*)(orow + wn * 32 + nt * 8 + 2 * tg) =
                    make_float2(acc[mt][nt][2], acc[mt][nt][3]);
        }
    }
}

// ---------------- combine ----------------
__global__ void k_combine(float* __restrict__ out) {
    int idx = blockIdx.x * blockDim.x + threadIdx.x;
    const int n4 = T_TOK * (HID / 4);
    if (idx >= n4) return;
    int t = idx / (HID / 4);
    int h = idx - t * (HID / 4);
    int s0 = d_tokslot[2 * t];
    int s1 = d_tokslot[2 * t + 1];
    float w0 = d_tokw[2 * t];
    float w1 = d_tokw[2 * t + 1];
    float4 y0 = ((const float4*)d_y)[(size_t)s0 * (HID / 4) + h];
    float4 y1 = ((const float4*)d_y)[(size_t)s1 * (HID / 4) + h];
    float4 o;
    o.x = w0 * y0.x + w1 * y1.x;
    o.y = w0 * y0.y + w1 * y1.y;
    o.z = w0 * y0.z + w1 * y1.z;
    o.w = w0 * y0.w + w1 * y1.w;
    ((float4*)out)[idx] = o;
}

// ---------------- launch ----------------
extern "C" void kernel_launch(void* const* d_in, const int* in_sizes, int n_in,
                              void* d_out, int out_size) {
    (void)in_sizes; (void)n_in; (void)out_size;
    const float* x  = (const float*)d_in[0];
    const float* rw = (const float*)d_in[1];
    const float* w1 = (const float*)d_in[2];
    const float* v1 = (const float*)d_in[3];
    const float* w2 = (const float*)d_in[4];
    float* out = (float*)d_out;

    const int SMEM1 = 2 * G1_BUFB;  // 147456 B
    const int SMEM2 = 2 * G2_BUFB;  // 110592 B
    cudaFuncSetAttribute(k_gemm1f, cudaFuncAttributeMaxDynamicSharedMemorySize, SMEM1);
    cudaFuncSetAttribute(k_gemm2, cudaFuncAttributeMaxDynamicSharedMemorySize, SMEM2);

    k_init<<<1, 32>>>();
    k_router<<<T_TOK / 4, 128>>>(x, rw);
    k_offsets<<<1, 32>>>();
    k_assign<<<T_TOK / 256, 256>>>();

    dim3 g1(FFN / 64, 32, NEXP);
    k_gemm1f<<<g1, 512, SMEM1>>>(x, w1, v1);

    dim3 g2(HID / 64, 32, NEXP);
    k_gemm2<<<g2, 256, SMEM2>>>(w2);

    k_combine<<<(T_TOK * (HID / 4)) / 256, 256>>>(out);
}